// round 17
// baseline (speedup 1.0000x reference)
#include <cuda_runtime.h>
#include <math.h>

#define B_ 32
#define P_ 24564
#define O_ 16
#define C_ 81
#define NB1_ 4096    // level-1 bins (12 bits: v >> 20)
#define CAP_ 6144    // phaseB candidate cap (smem)

// ---- scratch (device globals; no allocation) ----
__device__ float  g_bto[B_ * P_];
__device__ int    g_bti[B_ * P_];
__device__ __align__(16) float g_min_c[B_ * P_];
__device__ __align__(16) float g_min_o[B_ * P_];
__device__ unsigned g_hist[B_ * 2 * NB1_];        // level-1 histograms (1 MB)
__device__ unsigned long long g_key[B_ * O_];
__device__ double g_dacc[3];
__device__ int    g_npos[B_];
__device__ int    g_npos_tot;
__device__ int    g_ktot;

__global__ void k_init() {
    int i = blockIdx.x * 256 + threadIdx.x;
    if (i < B_ * 2 * NB1_) g_hist[i] = 0;
    if (i < B_ * O_) g_key[i] = 0ULL;
    if (i < 3)  g_dacc[i] = 0.0;
    if (i < B_) g_npos[i] = 0;
    if (i == 0) { g_npos_tot = 0; g_ktot = 0; }
}

__device__ __forceinline__ float iou_f(
    float px1, float py1, float px2, float py2, float parea,
    float tx1, float ty1, float tx2, float ty2, float tarea)
{
    float ix1 = fmaxf(tx1, px1), iy1 = fmaxf(ty1, py1);
    float ix2 = fminf(tx2, px2), iy2 = fminf(ty2, py2);
    float iw = fmaxf(__fsub_rn(ix2, ix1), 0.f);
    float ih = fmaxf(__fsub_rn(iy2, iy1), 0.f);
    float inter = __fmul_rn(iw, ih);
    float denom = __fsub_rn(__fadd_rn(tarea, parea), inter);
    return __fdiv_rn(inter, denom);
}

// ---- M1+M2 fused: per-prior argmax over truths AND per-truth argmax over priors
__global__ void k_iou_max(const float* __restrict__ priors,
                          const float* __restrict__ truths) {
    const int b = blockIdx.y;
    const int tid = threadIdx.x;
    const int lane = tid & 31, wid = tid >> 5;
    const int p = blockIdx.x * 256 + tid;
    const bool valid = (p < P_);

    __shared__ float tx1[O_], ty1[O_], tx2[O_], ty2[O_], tarea[O_];
    __shared__ unsigned long long s_key[8][O_];
    if (tid < O_) {
        const float* t = truths + ((size_t)b * O_ + tid) * 4;
        tx1[tid] = t[0]; ty1[tid] = t[1];
        tx2[tid] = t[2]; ty2[tid] = t[3];
        tarea[tid] = __fmul_rn(__fsub_rn(t[2], t[0]), __fsub_rn(t[3], t[1]));
    }
    __syncthreads();

    unsigned long long key[O_];
    float bv = -1.f; int bo = 0;
    if (valid) {
        const float* pr = priors + (size_t)p * 4;
        float cx = pr[0], cy = pr[1], w = pr[2], h = pr[3];
        float hw = __fmul_rn(w, 0.5f), hh = __fmul_rn(h, 0.5f);
        float px1 = __fsub_rn(cx, hw), py1 = __fsub_rn(cy, hh);
        float px2 = __fadd_rn(cx, hw), py2 = __fadd_rn(cy, hh);
        float parea = __fmul_rn(__fsub_rn(px2, px1), __fsub_rn(py2, py1));
#pragma unroll
        for (int o = 0; o < O_; o++) {
            float v = iou_f(px1, py1, px2, py2, parea,
                            tx1[o], ty1[o], tx2[o], ty2[o], tarea[o]);
            if (v > bv) { bv = v; bo = o; }  // strict > keeps FIRST max (o asc)
            key[o] = ((unsigned long long)__float_as_uint(v) << 32)
                   | (unsigned long long)(0xFFFFFFFFu - (unsigned)p);
        }
        size_t idx = (size_t)b * P_ + p;
        g_bto[idx] = bv; g_bti[idx] = bo;
    } else {
#pragma unroll
        for (int o = 0; o < O_; o++) key[o] = 0ULL;
    }

#pragma unroll
    for (int o = 0; o < O_; o++) {
        unsigned long long kk = key[o];
#pragma unroll
        for (int s = 16; s; s >>= 1) {
            unsigned long long other = __shfl_xor_sync(0xffffffffu, kk, s);
            if (other > kk) kk = other;
        }
        if (lane == 0) s_key[wid][o] = kk;
    }
    __syncthreads();
    if (tid < O_) {
        unsigned long long m = s_key[0][tid];
#pragma unroll
        for (int w = 1; w < 8; w++)
            if (s_key[w][tid] > m) m = s_key[w][tid];
        atomicMax(&g_key[b * O_ + tid], m);
    }
}

__device__ __forceinline__ float sl1(float d) {
    float ax = fabsf(d);
    return ax < 1.f ? 0.5f * ax * ax : ax - 0.5f;
}

// ---- phase A: LEAN warp-per-row CE. No smem tile, no barrier phasing.
//      8 rows per warp; conf_t decode via ballot; batched hist update.
__global__ void __launch_bounds__(256) k_phaseA(
        const float* __restrict__ loc,
        const float* __restrict__ conf,
        const float* __restrict__ obj,
        const float* __restrict__ priors,
        const float* __restrict__ truths,
        const int* __restrict__ labels) {
    const int b = blockIdx.y;
    const int lane = threadIdx.x & 31, wid = threadIdx.x >> 5;
    const int base = blockIdx.x * 64 + wid * 8;

    __shared__ int s_bp[O_], s_lab[O_];
    __shared__ double s_ll, s_pc, s_po;
    __shared__ int s_np;

    if (threadIdx.x == 0) { s_ll = 0.0; s_pc = 0.0; s_po = 0.0; s_np = 0; }
    if (threadIdx.x < O_) {
        s_bp[threadIdx.x]  = (int)(0xFFFFFFFFu -
            (unsigned)(g_key[b * O_ + threadIdx.x] & 0xFFFFFFFFu));
        s_lab[threadIdx.x] = labels[b * O_ + threadIdx.x];
    }
    __syncthreads();

    int nrows = P_ - base;
    if (nrows < 0) nrows = 0; else if (nrows > 8) nrows = 8;

    double a_ll = 0.0, a_pc = 0.0, a_po = 0.0; int a_np = 0;
    float mc[8], mo2[8];

#pragma unroll
    for (int i = 0; i < 8; i++) {
        float mcv = 0.f, mov = 0.f;
        if (i < nrows) {                       // warp-uniform predicate
            const int p = base + i;
            const size_t idx = (size_t)b * P_ + p;
            const float* r = conf + idx * (size_t)C_;

            float x0 = r[lane];
            float x1 = r[lane + 32];
            float x2 = (lane < 17) ? r[lane + 64] : 0.f;
            float e = __expf(x0) + __expf(x1) + ((lane < 17) ? __expf(x2) : 0.f);
#pragma unroll
            for (int s = 16; s; s >>= 1) e += __shfl_xor_sync(0xffffffffu, e, s);
            float lse = __logf(e);

            float v = g_bto[idx];              // warp-uniform broadcast loads
            int ti = g_bti[idx];
            unsigned m16 = __ballot_sync(0xffffffffu,
                                         lane < O_ && s_bp[lane] == p);
            if (m16) ti = 31 - __clz(m16);     // last matching truth wins
            int t = (m16 || v >= 0.5f) ? s_lab[ti] : 0;

            float xt = (t < 32) ? x0 : ((t < 64) ? x1 : x2);
            float pick = __shfl_sync(0xffffffffu, xt, t & 31);
            float cec = lse - pick;
            mcv = (t > 0) ? 0.f : cec;

            const float2 ob = *reinterpret_cast<const float2*>(obj + idx * 2);
            float lse2 = __logf(__expf(ob.x) + __expf(ob.y));
            float ceo = lse2 - ((t > 0) ? ob.y : ob.x);
            mov = (t > 0) ? 0.f : ceo;

            if (lane == 0) {
                g_min_c[idx] = mcv;
                g_min_o[idx] = mov;
                if (t > 0) {
                    a_pc += (double)cec; a_po += (double)ceo; a_np++;
                    const float* tr = truths + ((size_t)b * O_ + ti) * 4;
                    float mx1 = tr[0], my1 = tr[1], mx2 = tr[2], my2 = tr[3];
                    const float* pr = priors + (size_t)p * 4;
                    float gx = ((mx1 + mx2) * 0.5f - pr[0]) / (0.1f * pr[2]);
                    float gy = ((my1 + my2) * 0.5f - pr[1]) / (0.1f * pr[3]);
                    float gw = __logf((mx2 - mx1) / pr[2]) / 0.2f;
                    float gh = __logf((my2 - my1) / pr[3]) / 0.2f;
                    const float* ld = loc + idx * 4;
                    a_ll += (double)(sl1(ld[0] - gx) + sl1(ld[1] - gy)
                                   + sl1(ld[2] - gw) + sl1(ld[3] - gh));
                }
            }
        }
        mc[i] = mcv; mo2[i] = mov;
    }

    // batched level-1 histogram: lanes 0..7 carry mc[0..7], lanes 8..15 mo2[0..7]
    {
        const int L = lane & 7;
        float sc = (L == 0) ? mc[0] : (L == 1) ? mc[1] : (L == 2) ? mc[2] :
                   (L == 3) ? mc[3] : (L == 4) ? mc[4] : (L == 5) ? mc[5] :
                   (L == 6) ? mc[6] : mc[7];
        float so = (L == 0) ? mo2[0] : (L == 1) ? mo2[1] : (L == 2) ? mo2[2] :
                   (L == 3) ? mo2[3] : (L == 4) ? mo2[4] : (L == 5) ? mo2[5] :
                   (L == 6) ? mo2[6] : mo2[7];
        float hv = (lane < 8) ? sc : so;
        bool act = (lane < 16) && (L < nrows);
        unsigned amask = __ballot_sync(0xffffffffu, act);
        if (act) {
            unsigned bin = __float_as_uint(hv) >> 20;
            unsigned tag = (lane < 8) ? 0u : 0x10000u;
            unsigned mm = __match_any_sync(amask, tag | bin);
            if (lane == __ffs(mm) - 1) {
                unsigned arr = (lane < 8) ? 0u : 1u;
                atomicAdd(&g_hist[((unsigned)(b * 2 + arr) << 12) + bin],
                          __popc(mm));
            }
        }
    }

    unsigned any = __ballot_sync(0xffffffffu, a_np != 0);
    if (any && lane == 0) {
        atomicAdd(&s_ll, a_ll); atomicAdd(&s_pc, a_pc);
        atomicAdd(&s_po, a_po); atomicAdd(&s_np, a_np);
    }
    __syncthreads();
    if (threadIdx.x == 0 && s_np) {
        atomicAdd(&g_dacc[0], s_ll);
        atomicAdd(&g_dacc[1], s_pc);
        atomicAdd(&g_dacc[2], s_po);
        atomicAdd(&g_npos[b], s_np);
        atomicAdd(&g_npos_tot, s_np);
    }
}

// Parallel suffix-selection over an nb-bin smem histogram (warp 0 only).
__device__ __forceinline__ void select_bin(const unsigned* hist, int nb, int kk,
                                           int tid, int* sh_bin, int* sh_kk) {
    if (tid < 32) {
        const int seg = nb >> 5;
        const int b0 = tid * seg;
        int segsum = 0;
        for (int j = 0; j < seg; j++) segsum += (int)hist[b0 + j];
        int SI = segsum;
#pragma unroll
        for (int s = 1; s < 32; s <<= 1) {
            int v2 = __shfl_down_sync(0xffffffffu, SI, s);
            if (tid + s < 32) SI += v2;
        }
        int SI_above = SI - segsum;
        if (SI >= kk && SI_above < kk) {
            int c = kk - SI_above;
            for (int j = seg - 1; j >= 0; j--) {
                int h = (int)hist[b0 + j];
                if (c <= h) { *sh_bin = b0 + j; *sh_kk = c; break; }
                c -= h;
            }
        }
    }
}

// ---- phase B: top-k sum using the PREBUILT level-1 histogram (from phaseA).
//      One global pass (above-sum + warp-aggregated compaction), smem refine.
__global__ void __launch_bounds__(1024) k_phaseB() {
    const int b = blockIdx.x;
    const int arr = blockIdx.y;
    const int tid = threadIdx.x;
    const int NT = 1024;
    const int N4 = P_ / 4;              // 6141

    __shared__ unsigned hist[NB1_];     // 16 KB
    __shared__ unsigned cand[CAP_];     // 24 KB
    __shared__ int s_nc;
    __shared__ double s_above, s_res;
    __shared__ double wsum[32];
    __shared__ int sh_bin, sh_kk;

    int k = g_npos[b] * 3;
    if (k > P_ - 1) k = P_ - 1;

    const float* vals = (arr == 0 ? g_min_c : g_min_o) + (size_t)b * P_;
    const float4* v4 = reinterpret_cast<const float4*>(vals);

    double result = 0.0;
    if (k > 0) {
        const unsigned* gh = g_hist + ((unsigned)(b * 2 + arr) << 12);
        for (int i = tid; i < NB1_; i += NT) hist[i] = gh[i];
        if (tid == 0) { s_nc = 0; s_above = 0.0; s_res = 0.0; }
        __syncthreads();

        select_bin(hist, NB1_, k, tid, &sh_bin, &sh_kk);
        __syncthreads();
        const unsigned bin1 = (unsigned)sh_bin;
        int kk = sh_kk;
        const int nc = (int)hist[bin1];
        __syncthreads();

        unsigned T;
        if (nc <= CAP_) {
            // ---- single global pass: above-bin sum + warp-aggregated compact
            double above = 0.0;
            for (int i = tid; i < N4; i += NT) {
                float4 q = v4[i];
#pragma unroll
                for (int c4 = 0; c4 < 4; c4++) {
                    float f = (c4 == 0) ? q.x : (c4 == 1) ? q.y : (c4 == 2) ? q.z : q.w;
                    unsigned v = __float_as_uint(f);
                    unsigned h = v >> 20;
                    if (h > bin1) above += (double)f;
                    unsigned act = __activemask();
                    bool isc = (h == bin1);
                    unsigned mk = __ballot_sync(act, isc);
                    if (mk) {
                        int ldr = __ffs(mk) - 1;
                        int basep = 0;
                        if ((tid & 31) == ldr) basep = atomicAdd(&s_nc, __popc(mk));
                        basep = __shfl_sync(act, basep, ldr);
                        if (isc)
                            cand[basep + __popc(mk & ((1u << (tid & 31)) - 1u))] = v;
                    }
                }
            }
#pragma unroll
            for (int o = 16; o; o >>= 1) above += __shfl_xor_sync(0xffffffffu, above, o);
            if ((tid & 31) == 0 && above != 0.0) atomicAdd(&s_above, above);
            __syncthreads();

            // ---- refine level 2 (smem): bits [10,20) ----
            if (tid < 1024) hist[tid] = 0;
            __syncthreads();
            for (int j = tid; j < nc; j += NT)
                atomicAdd(&hist[(cand[j] >> 10) & 1023], 1u);
            __syncthreads();
            select_bin(hist, 1024, kk, tid, &sh_bin, &sh_kk);
            __syncthreads();
            const unsigned pref22 = (bin1 << 10) | (unsigned)sh_bin;  // bits [10,32)
            kk = sh_kk;
            __syncthreads();
            // ---- refine level 3 (smem): bits [0,10) ----
            if (tid < 1024) hist[tid] = 0;
            __syncthreads();
            for (int j = tid; j < nc; j += NT) {
                unsigned v = cand[j];
                if ((v >> 10) == pref22) atomicAdd(&hist[v & 1023], 1u);
            }
            __syncthreads();
            select_bin(hist, 1024, kk, tid, &sh_bin, &sh_kk);
            __syncthreads();
            T = (pref22 << 10) | (unsigned)sh_bin;
            kk = sh_kk;

            double loc = 0.0;
            for (int j = tid; j < nc; j += NT) {
                unsigned v = cand[j];
                if (v > T) loc += (double)__uint_as_float(v);
            }
#pragma unroll
            for (int o = 16; o; o >>= 1) loc += __shfl_xor_sync(0xffffffffu, loc, o);
            if ((tid & 31) == 0) wsum[tid >> 5] = loc;
            __syncthreads();
            if (tid < 32) {
                double v = wsum[tid];
#pragma unroll
                for (int o = 16; o; o >>= 1) v += __shfl_xor_sync(0xffffffffu, v, o);
                if (tid == 0)
                    s_res = v + (double)kk * (double)__uint_as_float(T);
            }
            __syncthreads();
            result = s_above + s_res;
        } else {
            // ---- fallback: global refinement passes (rare) ----
            unsigned prefix = bin1 << 20;
            for (int L = 0; L < 2; L++) {
                const int lo = (L == 0) ? 10 : 0;
                const int hi = (L == 0) ? 20 : 10;
                for (int i = tid; i < 1024; i += NT) hist[i] = 0;
                __syncthreads();
                for (int i = tid; i < N4; i += NT) {
                    float4 q = v4[i];
#pragma unroll
                    for (int c4 = 0; c4 < 4; c4++) {
                        float f = (c4 == 0) ? q.x : (c4 == 1) ? q.y : (c4 == 2) ? q.z : q.w;
                        unsigned v = __float_as_uint(f);
                        if ((v >> hi) == (prefix >> hi)) {
                            int bn = (v >> lo) & 1023;
                            unsigned mm = __match_any_sync(__activemask(), bn);
                            if ((tid & 31) == (__ffs(mm) - 1))
                                atomicAdd(&hist[bn], __popc(mm));
                        }
                    }
                }
                __syncthreads();
                select_bin(hist, 1024, kk, tid, &sh_bin, &sh_kk);
                __syncthreads();
                prefix |= ((unsigned)sh_bin) << lo;
                kk = sh_kk;
                __syncthreads();
            }
            T = prefix;
            double loc = 0.0;
            for (int i = tid; i < N4; i += NT) {
                float4 q = v4[i];
#pragma unroll
                for (int c4 = 0; c4 < 4; c4++) {
                    float f = (c4 == 0) ? q.x : (c4 == 1) ? q.y : (c4 == 2) ? q.z : q.w;
                    if (__float_as_uint(f) > T) loc += (double)f;
                }
            }
#pragma unroll
            for (int o = 16; o; o >>= 1) loc += __shfl_xor_sync(0xffffffffu, loc, o);
            if ((tid & 31) == 0) wsum[tid >> 5] = loc;
            __syncthreads();
            if (tid < 32) {
                double v = wsum[tid];
#pragma unroll
                for (int o = 16; o; o >>= 1) v += __shfl_xor_sync(0xffffffffu, v, o);
                if (tid == 0)
                    s_res = v + (double)kk * (double)__uint_as_float(T);
            }
            __syncthreads();
            result = s_res;
        }
    }

    if (tid == 0) {
        if (k > 0) atomicAdd(&g_dacc[arr == 0 ? 1 : 2], result);
        if (arr == 0) atomicAdd(&g_ktot, k);
    }
}

__global__ void k_final(float* __restrict__ out) {
    double N  = (double)(g_npos_tot > 1 ? g_npos_tot : 1);
    double N1 = (double)(g_ktot > 1 ? g_ktot : 1);
    out[0] = (float)(g_dacc[0] / N);
    out[1] = (float)(g_dacc[1] / N);
    out[2] = (float)(0.4 * g_dacc[2] / N1);
}

extern "C" void kernel_launch(void* const* d_in, const int* in_sizes, int n_in,
                              void* d_out, int out_size) {
    const float* loc    = (const float*)d_in[0];
    const float* conf   = (const float*)d_in[1];
    const float* obj    = (const float*)d_in[2];
    const float* priors = (const float*)d_in[3];
    const float* truths = (const float*)d_in[4];
    const int*   labels = (const int*)d_in[5];   // int32 (jax x64 disabled)

    k_init<<<(B_ * 2 * NB1_ + 255) / 256, 256>>>();
    k_iou_max<<<dim3((P_ + 255) / 256, B_), 256>>>(priors, truths);
    k_phaseA<<<dim3((P_ + 63) / 64, B_), 256>>>(loc, conf, obj,
                                                priors, truths, labels);
    k_phaseB<<<dim3(B_, 2), 1024>>>();
    k_final<<<1, 1>>>((float*)d_out);
}